// round 1
// baseline (speedup 1.0000x reference)
#include <cuda_runtime.h>

#define NB    65536
#define DIM   256
#define HID   64
#define ACT   18
#define NEXP  8
#define ROWS  128
#define NTHR  256
#define HSTR  132   // activation smem row stride (col-major [k][row]), padded
#define W6STR 20    // W6 smem row stride (>=18, float4-friendly)

#define SMEM_FLOATS (2 * HID * HSTR + HID * HID + HID * W6STR)
#define SMEM_BYTES  (SMEM_FLOATS * 4)

// ---------------- scratch (no allocations allowed) ----------------
__device__ int g_counts[NEXP];
__device__ int g_offsets[NEXP + 1];
__device__ int g_cursor[NEXP];
__device__ int g_perm[NB];

// ---------------- sort rows by expert ----------------
__global__ void k_zero() {
    if (threadIdx.x < NEXP) g_counts[threadIdx.x] = 0;
}

__global__ void k_hist(const int* __restrict__ rm) {
    __shared__ int s_cnt[NEXP];
    int t = threadIdx.x;
    if (t < NEXP) s_cnt[t] = 0;
    __syncthreads();
    int i = blockIdx.x * NTHR + t;
    atomicAdd(&s_cnt[rm[i]], 1);
    __syncthreads();
    if (t < NEXP) atomicAdd(&g_counts[t], s_cnt[t]);
}

__global__ void k_prefix() {
    int off = 0;
    for (int e = 0; e < NEXP; e++) {
        g_offsets[e] = off;
        g_cursor[e]  = off;
        off += g_counts[e];
    }
    g_offsets[NEXP] = off;
}

__global__ void k_scatter(const int* __restrict__ rm) {
    __shared__ int s_cnt[NEXP], s_base[NEXP];
    int t = threadIdx.x;
    if (t < NEXP) s_cnt[t] = 0;
    __syncthreads();
    int i = blockIdx.x * NTHR + t;
    int e = rm[i];
    int loc = atomicAdd(&s_cnt[e], 1);
    __syncthreads();
    if (t < NEXP) s_base[t] = atomicAdd(&g_cursor[t], s_cnt[t]);
    __syncthreads();
    g_perm[s_base[e] + loc] = i;
}

// ---------------- fused per-expert MLP ----------------
// grid: (tiles=NB/ROWS, NEXP). Block handles 128 rows of one expert.
// Thread tile: 8 rows x 4 cols. Activations col-major in smem.
__global__ void __launch_bounds__(NTHR, 2) k_moe(
    const float* __restrict__ X,
    const float* __restrict__ W1, const float* __restrict__ b1,
    const float* __restrict__ W2, const float* __restrict__ b2,
    const float* __restrict__ W3, const float* __restrict__ b3,
    const float* __restrict__ W4, const float* __restrict__ b4,
    const float* __restrict__ W5, const float* __restrict__ b5,
    const float* __restrict__ W6, const float* __restrict__ b6,
    float* __restrict__ out)
{
    extern __shared__ float smem[];
    float* sH0 = smem;                      // [HID][HSTR] activations ping
    float* sH1 = smem + HID * HSTR;         // pong
    float* sW  = smem + 2 * HID * HSTR;     // [64][64] current weight
    float* sW6 = sW + HID * HID;            // [64][W6STR]

    const int e    = blockIdx.y;
    const int off  = g_offsets[e];
    const int cnt  = g_offsets[e + 1] - off;
    const int tile = blockIdx.x;
    if (tile * ROWS >= cnt) return;
    const int nrows = min(ROWS, cnt - tile * ROWS);

    const int tid = threadIdx.x;
    const int rg  = tid & 15;       // row group 0..15
    const int cg  = tid >> 4;       // col group 0..15
    const int rb  = rg * 8;
    const int cb  = cg * 4;

    // X staging mapping: thread covers half a row's 64-float chunk
    const int lr   = tid >> 1;
    const int half = tid & 1;
    const float* xrow = nullptr;
    if (lr < nrows) {
        int grow = g_perm[off + tile * ROWS + lr];
        xrow = X + (size_t)grow * DIM;
    }

    float acc[8][4];
    #pragma unroll
    for (int i = 0; i < 8; i++)
        #pragma unroll
        for (int j = 0; j < 4; j++) acc[i][j] = 0.f;

    // ---------- Layer 1: [128,256] @ [256,64], 4 k-chunks of 64 ----------
    const float* W1e = W1 + (size_t)e * DIM * HID;
    for (int kc = 0; kc < 4; kc++) {
        // transpose-stage X chunk into sH0[k][row]
        #pragma unroll
        for (int v = 0; v < 8; v++) {
            float4 d = make_float4(0.f, 0.f, 0.f, 0.f);
            if (xrow) d = *(const float4*)(xrow + kc * 64 + half * 32 + v * 4);
            int k0 = half * 32 + v * 4;
            sH0[(k0 + 0) * HSTR + lr] = d.x;
            sH0[(k0 + 1) * HSTR + lr] = d.y;
            sH0[(k0 + 2) * HSTR + lr] = d.z;
            sH0[(k0 + 3) * HSTR + lr] = d.w;
        }
        // stage W1 chunk (contiguous 64x64)
        const float4* wsrc = (const float4*)(W1e + kc * 64 * HID);
        #pragma unroll
        for (int v = 0; v < 4; v++)
            ((float4*)sW)[tid + v * NTHR] = wsrc[tid + v * NTHR];
        __syncthreads();

        #pragma unroll 16
        for (int k = 0; k < 64; k++) {
            float4 wv = *(const float4*)(sW + k * HID + cb);
            float4 ha = *(const float4*)(sH0 + k * HSTR + rb);
            float4 hb = *(const float4*)(sH0 + k * HSTR + rb + 4);
            float w[4] = {wv.x, wv.y, wv.z, wv.w};
            float h[8] = {ha.x, ha.y, ha.z, ha.w, hb.x, hb.y, hb.z, hb.w};
            #pragma unroll
            for (int i = 0; i < 8; i++)
                #pragma unroll
                for (int j = 0; j < 4; j++)
                    acc[i][j] = fmaf(h[i], w[j], acc[i][j]);
        }
        __syncthreads();
    }
    // bias + relu -> sH0 (col-major)
    {
        const float* be = b1 + e * HID;
        #pragma unroll
        for (int j = 0; j < 4; j++) {
            float bj = be[cb + j];
            float4 lo = make_float4(fmaxf(acc[0][j] + bj, 0.f), fmaxf(acc[1][j] + bj, 0.f),
                                    fmaxf(acc[2][j] + bj, 0.f), fmaxf(acc[3][j] + bj, 0.f));
            float4 hi = make_float4(fmaxf(acc[4][j] + bj, 0.f), fmaxf(acc[5][j] + bj, 0.f),
                                    fmaxf(acc[6][j] + bj, 0.f), fmaxf(acc[7][j] + bj, 0.f));
            *(float4*)(sH0 + (cb + j) * HSTR + rb)     = lo;
            *(float4*)(sH0 + (cb + j) * HSTR + rb + 4) = hi;
        }
    }
    __syncthreads();

    // ---------- Layers 2..5: [128,64] @ [64,64], ping-pong ----------
    const float* Wls[4] = { W2 + (size_t)e * HID * HID, W3 + (size_t)e * HID * HID,
                            W4 + (size_t)e * HID * HID, W5 + (size_t)e * HID * HID };
    const float* bls[4] = { b2 + e * HID, b3 + e * HID, b4 + e * HID, b5 + e * HID };
    float* bufs[2] = { sH0, sH1 };

    #pragma unroll
    for (int l = 0; l < 4; l++) {
        float* sHc = bufs[l & 1];
        float* sHn = bufs[(l & 1) ^ 1];
        const float4* wsrc = (const float4*)(Wls[l]);
        #pragma unroll
        for (int v = 0; v < 4; v++)
            ((float4*)sW)[tid + v * NTHR] = wsrc[tid + v * NTHR];
        __syncthreads();

        #pragma unroll
        for (int i = 0; i < 8; i++)
            #pragma unroll
            for (int j = 0; j < 4; j++) acc[i][j] = 0.f;

        #pragma unroll 16
        for (int k = 0; k < 64; k++) {
            float4 wv = *(const float4*)(sW + k * HID + cb);
            float4 ha = *(const float4*)(sHc + k * HSTR + rb);
            float4 hb = *(const float4*)(sHc + k * HSTR + rb + 4);
            float w[4] = {wv.x, wv.y, wv.z, wv.w};
            float h[8] = {ha.x, ha.y, ha.z, ha.w, hb.x, hb.y, hb.z, hb.w};
            #pragma unroll
            for (int i = 0; i < 8; i++)
                #pragma unroll
                for (int j = 0; j < 4; j++)
                    acc[i][j] = fmaf(h[i], w[j], acc[i][j]);
        }
        const float* be = bls[l];
        #pragma unroll
        for (int j = 0; j < 4; j++) {
            float bj = be[cb + j];
            float4 lo = make_float4(fmaxf(acc[0][j] + bj, 0.f), fmaxf(acc[1][j] + bj, 0.f),
                                    fmaxf(acc[2][j] + bj, 0.f), fmaxf(acc[3][j] + bj, 0.f));
            float4 hi = make_float4(fmaxf(acc[4][j] + bj, 0.f), fmaxf(acc[5][j] + bj, 0.f),
                                    fmaxf(acc[6][j] + bj, 0.f), fmaxf(acc[7][j] + bj, 0.f));
            *(float4*)(sHn + (cb + j) * HSTR + rb)     = lo;
            *(float4*)(sHn + (cb + j) * HSTR + rb + 4) = hi;
        }
        __syncthreads();
    }

    // ---------- Layer 6: [128,64] @ [64,18], no relu ----------
    float* sHf = bufs[0];  // after 4 layers final activations are back in sH0
    const float* W6e = W6 + (size_t)e * HID * ACT;
    for (int i2 = tid; i2 < HID * ACT; i2 += NTHR)
        sW6[(i2 / ACT) * W6STR + (i2 % ACT)] = W6e[i2];
    __syncthreads();

    int pr[8];
    #pragma unroll
    for (int i = 0; i < 8; i++) {
        int r = rb + i;
        pr[i] = (r < nrows) ? g_perm[off + tile * ROWS + r] : -1;
    }

    if (cb < ACT) {
        float accO[8][4];
        #pragma unroll
        for (int i = 0; i < 8; i++)
            #pragma unroll
            for (int j = 0; j < 4; j++) accO[i][j] = 0.f;

        #pragma unroll 16
        for (int k = 0; k < 64; k++) {
            float4 ha = *(const float4*)(sHf + k * HSTR + rb);
            float4 hb = *(const float4*)(sHf + k * HSTR + rb + 4);
            float h[8] = {ha.x, ha.y, ha.z, ha.w, hb.x, hb.y, hb.z, hb.w};
            float w[4];
            #pragma unroll
            for (int j = 0; j < 4; j++) w[j] = sW6[k * W6STR + cb + j];
            #pragma unroll
            for (int i = 0; i < 8; i++)
                #pragma unroll
                for (int j = 0; j < 4; j++)
                    accO[i][j] = fmaf(h[i], w[j], accO[i][j]);
        }
        const float* b6e = b6 + e * ACT;
        #pragma unroll
        for (int j = 0; j < 4; j++) {
            int c = cb + j;
            if (c < ACT) {
                float bj = b6e[c];
                #pragma unroll
                for (int i = 0; i < 8; i++)
                    if (pr[i] >= 0) out[(size_t)pr[i] * ACT + c] = accO[i][j] + bj;
            }
        }
    }
}

extern "C" void kernel_launch(void* const* d_in, const int* in_sizes, int n_in,
                              void* d_out, int out_size) {
    const float* X  = (const float*)d_in[0];
    const int*   rm = (const int*)d_in[1];
    const float* W1 = (const float*)d_in[2];  const float* b1 = (const float*)d_in[3];
    const float* W2 = (const float*)d_in[4];  const float* b2 = (const float*)d_in[5];
    const float* W3 = (const float*)d_in[6];  const float* b3 = (const float*)d_in[7];
    const float* W4 = (const float*)d_in[8];  const float* b4 = (const float*)d_in[9];
    const float* W5 = (const float*)d_in[10]; const float* b5 = (const float*)d_in[11];
    const float* W6 = (const float*)d_in[12]; const float* b6 = (const float*)d_in[13];
    float* out = (float*)d_out;

    cudaFuncSetAttribute(k_moe, cudaFuncAttributeMaxDynamicSharedMemorySize, SMEM_BYTES);

    k_zero<<<1, 32>>>();
    k_hist<<<NB / NTHR, NTHR>>>(rm);
    k_prefix<<<1, 1>>>();
    k_scatter<<<NB / NTHR, NTHR>>>(rm);

    dim3 grid(NB / ROWS, NEXP);
    k_moe<<<grid, NTHR, SMEM_BYTES>>>(X, W1, b1, W2, b2, W3, b3, W4, b4,
                                      W5, b5, W6, b6, out);
}